// round 15
// baseline (speedup 1.0000x reference)
#include <cuda_runtime.h>
#include <cuda_bf16.h>
#include <cuda_fp16.h>
#include <stdint.h>

#define BB 4
#define NNq 4096

// ---------------- device scratch ----------------
__device__ float g_q[BB*64*NNq];
__device__ float g_k[BB*64*NNq];
__device__ float g_m[BB*NNq];
__device__ __align__(16) __nv_bfloat16 g_qTb[(size_t)BB*NNq*64];  // [b][n][c] whitened
__device__ __align__(16) __nv_bfloat16 g_kTb[(size_t)BB*NNq*64];  // [b][n][c] whitened
__device__ __align__(16) __half g_vF16[(size_t)BB*64*NNq];        // [b][c][n]
__device__ __align__(16) __half g_P16[(size_t)BB*NNq*NNq];        // 128 MiB, symmetric per b
__device__ float g_rowsum[BB*NNq];
__device__ float g_invrs[BB*NNq];
__device__ float g_qsum[BB*64];
__device__ float g_ksum[BB*64];

// ---------------- helpers ----------------
__device__ __forceinline__ float fexp(float v){
    float y = v * 1.44269504088896341f;
    float t = y + 12582912.0f;
    int   e = __float_as_int(t) - 0x4B400000;
    float f = y - (t - 12582912.0f);
    float p = 0.00961804886f;
    p = p*f + 0.05550410866f;
    p = p*f + 0.24022650696f;
    p = p*f + 0.69314718056f;
    p = p*f + 1.0f;
    return __int_as_float(__float_as_int(p) + (e << 23));
}

__device__ __forceinline__ void mma16816(float c[4], const uint32_t a[4],
                                         uint32_t b0, uint32_t b1){
    asm volatile(
        "mma.sync.aligned.m16n8k16.row.col.f32.bf16.bf16.f32 "
        "{%0,%1,%2,%3}, {%4,%5,%6,%7}, {%8,%9}, {%0,%1,%2,%3};"
        : "+f"(c[0]), "+f"(c[1]), "+f"(c[2]), "+f"(c[3])
        : "r"(a[0]), "r"(a[1]), "r"(a[2]), "r"(a[3]), "r"(b0), "r"(b1));
}
__device__ __forceinline__ void mma16816h(float c[4], const uint32_t a[4],
                                          uint32_t b0, uint32_t b1){
    asm volatile(
        "mma.sync.aligned.m16n8k16.row.col.f32.f16.f16.f32 "
        "{%0,%1,%2,%3}, {%4,%5,%6,%7}, {%8,%9}, {%0,%1,%2,%3};"
        : "+f"(c[0]), "+f"(c[1]), "+f"(c[2]), "+f"(c[3])
        : "r"(a[0]), "r"(a[1]), "r"(a[2]), "r"(a[3]), "r"(b0), "r"(b1));
}

__device__ __forceinline__ void ldsm_x4(uint32_t r[4], uint32_t addr){
    asm volatile("ldmatrix.sync.aligned.m8n8.x4.shared.b16 {%0,%1,%2,%3}, [%4];"
        : "=r"(r[0]), "=r"(r[1]), "=r"(r[2]), "=r"(r[3]) : "r"(addr));
}

#define CPA16(d, s) asm volatile("cp.async.cg.shared.global [%0], [%1], 16;" \
        :: "r"((uint32_t)(d)), "l"(s) : "memory")
#define CPCOMMIT()  asm volatile("cp.async.commit_group;" ::: "memory")
#define CPWAIT0()   asm volatile("cp.async.wait_group 0;" ::: "memory")

// ---------------- K0: zero accumulators ----------------
__global__ void DNL_k0_zero(){
    int i = blockIdx.x*blockDim.x + threadIdx.x;
    if (i < BB*NNq) g_rowsum[i] = 0.0f;
    if (i < BB*64){ g_qsum[i] = 0.0f; g_ksum[i] = 0.0f; }
}

// ---------------- K1: q,k,v(fp16),m and BN(wx) -> out; 64-wide tiles ------------
__device__ __forceinline__ void conv_acc2(const float* __restrict__ wsm,
                                          const float* __restrict__ xs,
                                          const float* __restrict__ bias,
                                          int o0, int n0, float acc[2][8]){
    #pragma unroll
    for (int i=0;i<2;i++){
        float bv = bias[o0+i];
        #pragma unroll
        for (int j=0;j<8;j++) acc[i][j] = bv;
    }
    #pragma unroll 8
    for (int c=0;c<64;c++){
        float4 x0 = *(const float4*)(xs + c*68 + n0);
        float4 x1 = *(const float4*)(xs + c*68 + n0 + 4);
        #pragma unroll
        for (int i=0;i<2;i++){
            float w = wsm[(o0+i)*65 + c];
            acc[i][0] += w*x0.x; acc[i][1] += w*x0.y;
            acc[i][2] += w*x0.z; acc[i][3] += w*x0.w;
            acc[i][4] += w*x1.x; acc[i][5] += w*x1.y;
            acc[i][6] += w*x1.z; acc[i][7] += w*x1.w;
        }
    }
}

__global__ __launch_bounds__(256) void DNL_k1(
    const float* __restrict__ x,
    const float* __restrict__ qw, const float* __restrict__ qb,
    const float* __restrict__ kw, const float* __restrict__ kb,
    const float* __restrict__ mw, const float* __restrict__ mb,
    const float* __restrict__ vw, const float* __restrict__ vb,
    const float* __restrict__ ww, const float* __restrict__ wb,
    const float* __restrict__ bng, const float* __restrict__ bnb,
    const float* __restrict__ bnrm, const float* __restrict__ bnrv,
    float* __restrict__ out)
{
    extern __shared__ float sm[];
    float* xs  = sm;               // 64*68
    float* wq  = xs  + 64*68;
    float* wk  = wq  + 64*65;
    float* wv  = wk  + 64*65;
    float* wwt = wv  + 64*65;
    float* qs  = wwt + 64*65;      // 64
    float* ks  = qs  + 64;         // 64

    int b = blockIdx.y, nt = blockIdx.x;   // nt in 0..63
    int nb = nt << 6;
    int tid = threadIdx.x;

    if (tid < 64){ qs[tid] = 0.0f; ks[tid] = 0.0f; }
    for (int idx = tid; idx < 64*64; idx += 256){
        int c = idx >> 6, pos = idx & 63;
        xs[c*68 + pos] = x[(((b<<6)+c)<<12) + nb + pos];
    }
    for (int idx = tid; idx < 64*64; idx += 256){
        int o = idx >> 6, c = idx & 63;
        int so = o*65 + c;
        wq[so] = qw[idx]; wk[so] = kw[idx]; wv[so] = vw[idx]; wwt[so] = ww[idx];
    }
    __syncthreads();

    if (tid < 64){
        float a = mb[0];
        #pragma unroll 8
        for (int c=0;c<64;c++) a += mw[c]*xs[c*68 + tid];
        g_m[(b<<12) + nb + tid] = a;
    }

    int tx = tid & 7, ty = tid >> 3;
    int n0 = tx << 3, o0 = ty << 1;
    float acc[2][8];

    conv_acc2(wq, xs, qb, o0, n0, acc);
    #pragma unroll
    for (int i=0;i<2;i++){
        float* dst = g_q + ((((size_t)(b<<6)+o0+i)<<12) + nb + n0);
        *(float4*)dst     = make_float4(acc[i][0],acc[i][1],acc[i][2],acc[i][3]);
        *(float4*)(dst+4) = make_float4(acc[i][4],acc[i][5],acc[i][6],acc[i][7]);
        float s = acc[i][0]+acc[i][1]+acc[i][2]+acc[i][3]
                 +acc[i][4]+acc[i][5]+acc[i][6]+acc[i][7];
        atomicAdd(&qs[o0+i], s);
    }
    conv_acc2(wk, xs, kb, o0, n0, acc);
    #pragma unroll
    for (int i=0;i<2;i++){
        float* dst = g_k + ((((size_t)(b<<6)+o0+i)<<12) + nb + n0);
        *(float4*)dst     = make_float4(acc[i][0],acc[i][1],acc[i][2],acc[i][3]);
        *(float4*)(dst+4) = make_float4(acc[i][4],acc[i][5],acc[i][6],acc[i][7]);
        float s = acc[i][0]+acc[i][1]+acc[i][2]+acc[i][3]
                 +acc[i][4]+acc[i][5]+acc[i][6]+acc[i][7];
        atomicAdd(&ks[o0+i], s);
    }
    // V -> fp16 directly
    conv_acc2(wv, xs, vb, o0, n0, acc);
    #pragma unroll
    for (int i=0;i<2;i++){
        __half* dst = g_vF16 + ((((size_t)(b<<6)+o0+i)<<12) + nb + n0);
        __half2 h0 = __floats2half2_rn(acc[i][0], acc[i][1]);
        __half2 h1 = __floats2half2_rn(acc[i][2], acc[i][3]);
        __half2 h2 = __floats2half2_rn(acc[i][4], acc[i][5]);
        __half2 h3 = __floats2half2_rn(acc[i][6], acc[i][7]);
        uint4 pk;
        pk.x = *(uint32_t*)&h0; pk.y = *(uint32_t*)&h1;
        pk.z = *(uint32_t*)&h2; pk.w = *(uint32_t*)&h3;
        *(uint4*)dst = pk;
    }
    conv_acc2(wwt, xs, wb, o0, n0, acc);
    #pragma unroll
    for (int i=0;i<2;i++){
        int o = o0 + i;
        float sc = bng[o] * rsqrtf(bnrv[o] + 1e-5f);
        float sh = bnb[o] - bnrm[o]*sc;
        float* dst = out + (((size_t)(b<<6)+o)<<12) + nb + n0;
        *(float4*)dst     = make_float4(acc[i][0]*sc+sh, acc[i][1]*sc+sh,
                                        acc[i][2]*sc+sh, acc[i][3]*sc+sh);
        *(float4*)(dst+4) = make_float4(acc[i][4]*sc+sh, acc[i][5]*sc+sh,
                                        acc[i][6]*sc+sh, acc[i][7]*sc+sh);
    }
    __syncthreads();
    if (tid < 64){
        atomicAdd(&g_qsum[(b<<6)+tid], qs[tid]);
        atomicAdd(&g_ksum[(b<<6)+tid], ks[tid]);
    }
}

// ---------------- K2b: whiten + transpose + bf16 -------------------------------
__global__ __launch_bounds__(256) void DNL_k2b(){
    __shared__ float sq[64*65], sk[64*65], mq[64], mk[64];
    int b = blockIdx.y, nt = blockIdx.x, tid = threadIdx.x;
    if (tid<64){ mq[tid]=g_qsum[(b<<6)+tid]*(1.f/NNq); mk[tid]=g_ksum[(b<<6)+tid]*(1.f/NNq); }
    for (int i=tid;i<4096;i+=256){
        int c=i>>6, n=i&63;
        sq[c*65+n]=g_q[(((size_t)(b<<6)+c)<<12)+(nt<<6)+n];
        sk[c*65+n]=g_k[(((size_t)(b<<6)+c)<<12)+(nt<<6)+n];
    }
    __syncthreads();
    for (int i=tid;i<2048;i+=256){
        int n=i>>5, c=(i&31)<<1;
        size_t row = (size_t)(b<<12)+(nt<<6)+n;
        __nv_bfloat162 hq = __floats2bfloat162_rn(sq[c*65+n]-mq[c], sq[(c+1)*65+n]-mq[c+1]);
        __nv_bfloat162 hk = __floats2bfloat162_rn(sk[c*65+n]-mk[c], sk[(c+1)*65+n]-mk[c+1]);
        *(__nv_bfloat162*)(g_qTb + row*64 + c) = hq;
        *(__nv_bfloat162*)(g_kTb + row*64 + c) = hk;
    }
}

// ---------------- K3r: rowsums only, split accumulators, 3 CTA/SM ---------------
// grid (jh=4, it=32, b=4) = 512 blocks, 256 threads, dyn smem 55296 B
__global__ __launch_bounds__(256,3) void DNL_k3r(){
    extern __shared__ char s3[];
    uint32_t sA = (uint32_t)__cvta_generic_to_shared(s3);
    int jh=blockIdx.x, it=blockIdx.y, b=blockIdx.z;
    int tid=threadIdx.x;
    int w = tid>>5, lane = tid&31, g = lane>>2, t = lane&3;
    int wn = w<<4;

    uint32_t aAddr = sA + (uint32_t)((wn + (lane&7) + ((lane>>3)&1)*8)*144
                                     + ((lane>>4)&1)*16);
    uint32_t bRel  = (uint32_t)(((lane&7) + (lane>>4)*8)*144 + ((lane>>3)&1)*16);

    for (int i=tid;i<1024;i+=256){
        int r=i>>3, u=i&7;
        CPA16(sA + r*144 + u*16,
              g_kTb + ((size_t)(b<<12)+(it<<7)+r)*64 + u*8);
    }
    for (int i=tid;i<1024;i+=256){
        int r=i>>3, u=i&7;
        CPA16(sA + 18432 + r*144 + u*16,
              g_qTb + ((size_t)(b<<12)+(jh<<10)+r)*64 + u*8);
    }
    CPCOMMIT();

    float rs0=0.f, rs1=0.f;
    for (int mc2=0; mc2<8; mc2++){
        CPWAIT0();
        __syncthreads();
        if (mc2 < 7){
            uint32_t dst = sA + 18432 + (((mc2+1)&1) ? 18432u : 0u);
            for (int i=tid;i<1024;i+=256){
                int r=i>>3, u=i&7;
                CPA16(dst + r*144 + u*16,
                      g_qTb + ((size_t)(b<<12)+(jh<<10)+((mc2+1)<<7)+r)*64 + u*8);
            }
            CPCOMMIT();
        }
        uint32_t bAddr = sA + 18432 + ((mc2&1) ? 18432u : 0u) + bRel;

        #pragma unroll
        for (int h=0; h<2; h++){
            float a[8][4];
            #pragma unroll
            for (int cs=0;cs<8;cs++){ a[cs][0]=0.f; a[cs][1]=0.f; a[cs][2]=0.f; a[cs][3]=0.f; }
            #pragma unroll
            for (int k=0;k<4;k++){
                uint32_t af[4];
                ldsm_x4(af, aAddr + k*32);
                #pragma unroll
                for (int u=0;u<4;u++){
                    uint32_t bf[4];
                    ldsm_x4(bf, bAddr + (4*h+u)*(16*144) + k*32);
                    mma16816(a[2*u],   af, bf[0], bf[1]);
                    mma16816(a[2*u+1], af, bf[2], bf[3]);
                }
            }
            #pragma unroll
            for (int cs=0;cs<8;cs++){
                rs0 += fexp(a[cs][0]) + fexp(a[cs][1]);
                rs1 += fexp(a[cs][2]) + fexp(a[cs][3]);
            }
        }
    }
    rs0 += __shfl_xor_sync(0xffffffffu, rs0, 1);
    rs0 += __shfl_xor_sync(0xffffffffu, rs0, 2);
    rs1 += __shfl_xor_sync(0xffffffffu, rs1, 1);
    rs1 += __shfl_xor_sync(0xffffffffu, rs1, 2);
    if (t == 0){
        atomicAdd(&g_rowsum[(b<<12)+(it<<7)+wn+g],   rs0);
        atomicAdd(&g_rowsum[(b<<12)+(it<<7)+wn+g+8], rs1);
    }
}

// ---------------- K3b: reciprocal row sums --------------------------------------
__global__ void DNL_k3b(){
    int i = blockIdx.x*blockDim.x + threadIdx.x;
    if (i < BB*NNq) g_invrs[i] = 1.0f / g_rowsum[i];
}

// ---------------- K3c: P16[b][n][m] = exp(m_b[n]m_b[m]) / sum_b' ----------------
__global__ __launch_bounds__(256) void DNL_k3c(){
    size_t tt = ((size_t)blockIdx.x << 8) + threadIdx.x;   // 8.4M
    int n  = (int)(tt >> 11);
    int m0 = (int)((tt & 2047) << 1);
    float a0=g_m[n], a1=g_m[4096+n], a2=g_m[8192+n], a3=g_m[12288+n];
    float p0=g_m[m0],       q0=g_m[m0+1];
    float p1=g_m[4096+m0],  q1=g_m[4097+m0];
    float p2=g_m[8192+m0],  q2=g_m[8193+m0];
    float p3=g_m[12288+m0], q3=g_m[12289+m0];
    float e00=fexp(a0*p0), e01=fexp(a0*q0);
    float e10=fexp(a1*p1), e11=fexp(a1*q1);
    float e20=fexp(a2*p2), e21=fexp(a2*q2);
    float e30=fexp(a3*p3), e31=fexp(a3*q3);
    float s0=e00+e10+e20+e30, s1=e01+e11+e21+e31;
    float r0 = __int_as_float(0x7EF311C3 - __float_as_int(s0));
    r0 = r0*(2.0f-s0*r0); r0 = r0*(2.0f-s0*r0);
    float r1 = __int_as_float(0x7EF311C3 - __float_as_int(s1));
    r1 = r1*(2.0f-s1*r1); r1 = r1*(2.0f-s1*r1);
    size_t base = ((size_t)n<<12) + m0;
    *(__half2*)(g_P16 + base)               = __floats2half2_rn(e00*r0, e01*r1);
    *(__half2*)(g_P16 + (1ULL<<24) + base)  = __floats2half2_rn(e10*r0, e11*r1);
    *(__half2*)(g_P16 + (2ULL<<24) + base)  = __floats2half2_rn(e20*r0, e21*r1);
    *(__half2*)(g_P16 + (3ULL<<24) + base)  = __floats2half2_rn(e30*r0, e31*r1);
}

// ---------------- K4r: pipelined fused S -> F(+P16) -> out += V*F ---------------
// grid (b=4 fastest, mt=64), 256 threads, dyn smem 74240 B
#define K4_SQ    0
#define K4_SFH   9216
#define K4_ST0   18432
#define K4_ST1   46336
#define K4_STK   0
#define K4_STV   9216
#define K4_STP   18432
#define K4_SIR   27648
// stage size = 27904

__device__ __forceinline__ void k4_issue_stage(uint32_t dstBase, int b, int nbase,
                                               int mbase, int tid){
    for (int i=tid;i<512;i+=256){
        int r=i>>3, u=i&7;
        CPA16(dstBase + K4_STK + r*144 + u*16,
              g_kTb + ((size_t)(b<<12)+nbase+r)*64 + u*8);
    }
    for (int i=tid;i<512;i+=256){
        int c=i>>3, u=i&7;
        CPA16(dstBase + K4_STV + c*144 + u*16,
              g_vF16 + (((size_t)(b<<6)+c)<<12) + nbase + u*8);
    }
    for (int i=tid;i<512;i+=256){
        int r=i>>3, u=i&7;     // row r = local m; symmetric P -> n contiguous
        CPA16(dstBase + K4_STP + r*144 + u*16,
              g_P16 + ((size_t)b<<24) + ((size_t)(mbase+r)<<12) + nbase + u*8);
    }
    if (tid < 16)
        CPA16(dstBase + K4_SIR + tid*16, g_invrs + (b<<12) + nbase + tid*4);
}

__global__ __launch_bounds__(256,2) void DNL_k4r(float* __restrict__ out){
    extern __shared__ char s4[];
    uint32_t sA = (uint32_t)__cvta_generic_to_shared(s4);
    int b = blockIdx.x, mt = blockIdx.y;
    int mbase = mt<<6;
    int tid = threadIdx.x;
    int w = tid>>5, lane = tid&31, g = lane>>2, t = lane&3;
    int wn = (w&3)<<4;
    int wm = (w>>2)<<5;

    uint32_t aRow = (uint32_t)((wn + (lane&7) + ((lane>>3)&1)*8)*144
                               + ((lane>>4)&1)*16);
    uint32_t bRow = (uint32_t)((wm + (lane&7) + (lane>>4)*8)*144
                               + ((lane>>3)&1)*16);
    uint32_t bQ  = sA + K4_SQ  + bRow;
    uint32_t bFH = sA + K4_SFH + bRow;

    // prologue
    for (int i=tid;i<512;i+=256){
        int r=i>>3, u=i&7;
        CPA16(sA + K4_SQ + r*144 + u*16,
              g_qTb + ((size_t)(b<<12)+mbase+r)*64 + u*8);
    }
    k4_issue_stage(sA + K4_ST0, b, 0, mbase, tid);
    CPCOMMIT();

    float acc2[4][4];
    #pragma unroll
    for (int mc=0;mc<4;mc++){ acc2[mc][0]=0.f; acc2[mc][1]=0.f; acc2[mc][2]=0.f; acc2[mc][3]=0.f; }

    for (int ch=0; ch<64; ch++){
        CPWAIT0();
        __syncthreads();   // data landed; all warps past mma2(ch-1)

        int stgOff = (ch&1) ? K4_ST1 : K4_ST0;
        uint32_t stgA = sA + stgOff;
        if (ch < 63){
            k4_issue_stage(sA + (((ch+1)&1) ? K4_ST1 : K4_ST0), b, (ch+1)<<6, mbase, tid);
            CPCOMMIT();
        }

        // ---- mma1: S = K x Q^T (bf16) ----
        float a1[4][4];
        #pragma unroll
        for (int mc=0;mc<4;mc++){ a1[mc][0]=0.f; a1[mc][1]=0.f; a1[mc][2]=0.f; a1[mc][3]=0.f; }
        uint32_t aK = stgA + K4_STK + aRow;
        #pragma unroll
        for (int k=0;k<4;k++){
            uint32_t af[4], bf0[4], bf1[4];
            ldsm_x4(af,  aK + k*32);
            ldsm_x4(bf0, bQ + k*32);
            ldsm_x4(bf1, bQ + 16*144 + k*32);
            mma16816(a1[0], af, bf0[0], bf0[1]);
            mma16816(a1[1], af, bf0[2], bf0[3]);
            mma16816(a1[2], af, bf1[0], bf1[1]);
            mma16816(a1[3], af, bf1[2], bf1[3]);
        }
        // ---- construct F = fexp(S)*irs + P16 -> FH fp16 [m][n] ----
        const __half* Ps   = (const __half*)(s4 + stgOff + K4_STP);
        const float*  irsS = (const float*)(s4 + stgOff + K4_SIR);
        int nl0 = wn+g, nl1 = nl0+8;
        float ir0 = irsS[nl0], ir1 = irsS[nl1];
        __half* FH = (__half*)(s4+K4_SFH);
        #pragma unroll
        for (int mc=0;mc<4;mc++){
            int ml = wm + mc*8 + 2*t;
            float f0 = fexp(a1[mc][0])*ir0 + __half2float(Ps[ml*72     + nl0]);
            float f1 = fexp(a1[mc][1])*ir0 + __half2float(Ps[(ml+1)*72 + nl0]);
            float f2 = fexp(a1[mc][2])*ir1 + __half2float(Ps[ml*72     + nl1]);
            float f3 = fexp(a1[mc][3])*ir1 + __half2float(Ps[(ml+1)*72 + nl1]);
            FH[ml*72     + nl0] = __float2half_rn(f0);
            FH[(ml+1)*72 + nl0] = __float2half_rn(f1);
            FH[ml*72     + nl1] = __float2half_rn(f2);
            FH[(ml+1)*72 + nl1] = __float2half_rn(f3);
        }
        __syncthreads();   // F visible

        // ---- mma2: acc2 += V16 * FH  (fp16, single pass) ----
        uint32_t aV = stgA + K4_STV + aRow;
        #pragma unroll
        for (int k=0;k<4;k++){
            uint32_t ah[4], bh0[4], bh1[4];
            ldsm_x4(ah,  aV + k*32);
            ldsm_x4(bh0, bFH + k*32);
            ldsm_x4(bh1, bFH + 16*144 + k*32);
            mma16816h(acc2[0], ah, bh0[0], bh0[1]);
            mma16816h(acc2[1], ah, bh0[2], bh0[3]);
            mma16816h(acc2[2], ah, bh1[0], bh1[1]);
            mma16816h(acc2[3], ah, bh1[2], bh1[3]);
        }
    }

    // epilogue: RMW onto BN residual
    #pragma unroll
    for (int mc=0;mc<4;mc++){
        int cg = wn + g;
        int mg = mbase + wm + mc*8 + 2*t;
        float* d0 = out + (((size_t)(b<<6)+cg)<<12) + mg;
        float2 o0 = *(const float2*)d0;
        o0.x += acc2[mc][0]; o0.y += acc2[mc][1];
        *(float2*)d0 = o0;
        float* d1 = out + (((size_t)(b<<6)+cg+8)<<12) + mg;
        float2 o1 = *(const float2*)d1;
        o1.x += acc2[mc][2]; o1.y += acc2[mc][3];
        *(float2*)d1 = o1;
    }
}

// ---------------- host launcher -------------------------------------------------
extern "C" void kernel_launch(void* const* d_in, const int* in_sizes, int n_in,
                              void* d_out, int out_size)
{
    const float* x    = (const float*)d_in[0];
    const float* qw   = (const float*)d_in[1];
    const float* qb   = (const float*)d_in[2];
    const float* kw   = (const float*)d_in[3];
    const float* kb   = (const float*)d_in[4];
    const float* mw   = (const float*)d_in[5];
    const float* mb   = (const float*)d_in[6];
    const float* vw   = (const float*)d_in[7];
    const float* vb   = (const float*)d_in[8];
    const float* ww   = (const float*)d_in[9];
    const float* wb   = (const float*)d_in[10];
    const float* bng  = (const float*)d_in[11];
    const float* bnb  = (const float*)d_in[12];
    const float* bnrm = (const float*)d_in[13];
    const float* bnrv = (const float*)d_in[14];
    float* out = (float*)d_out;

    const int SM1 = 84480;
    const int SM3 = 55296;
    const int SM4 = 74240;
    cudaFuncSetAttribute(DNL_k1,  cudaFuncAttributeMaxDynamicSharedMemorySize, SM1);
    cudaFuncSetAttribute(DNL_k3r, cudaFuncAttributeMaxDynamicSharedMemorySize, SM3);
    cudaFuncSetAttribute(DNL_k4r, cudaFuncAttributeMaxDynamicSharedMemorySize, SM4);

    DNL_k0_zero<<<64, 256>>>();
    DNL_k1<<<dim3(64,4), 256, SM1>>>(x, qw,qb, kw,kb, mw,mb, vw,vb, ww,wb,
                                     bng,bnb,bnrm,bnrv, out);
    DNL_k2b<<<dim3(64,4), 256>>>();
    DNL_k3r<<<dim3(4,32,4), 256, SM3>>>();
    DNL_k3b<<<64, 256>>>();
    DNL_k3c<<<32768, 256>>>();
    DNL_k4r<<<dim3(4,64), 256, SM4>>>(out);
}

// round 16
// speedup vs baseline: 1.0706x; 1.0706x over previous
#include <cuda_runtime.h>
#include <cuda_bf16.h>
#include <cuda_fp16.h>
#include <stdint.h>

#define BB 4
#define NNq 4096

// ---------------- device scratch ----------------
__device__ float g_q[BB*64*NNq];
__device__ float g_k[BB*64*NNq];
__device__ float g_m[BB*NNq];
__device__ __align__(16) __nv_bfloat16 g_qTb[(size_t)BB*NNq*64];  // [b][n][c] whitened
__device__ __align__(16) __nv_bfloat16 g_kTb[(size_t)BB*NNq*64];  // [b][n][c] whitened
__device__ __align__(16) __half g_vF16[(size_t)BB*64*NNq];        // [b][c][n]
__device__ __align__(16) __half g_P16[(size_t)BB*NNq*NNq];        // 128 MiB, symmetric per b
__device__ float g_rowsum[BB*NNq];
__device__ float g_invrs[BB*NNq];
__device__ float g_qsum[BB*64];
__device__ float g_ksum[BB*64];

// ---------------- helpers ----------------
__device__ __forceinline__ float fexp(float v){
    float y = v * 1.44269504088896341f;
    float t = y + 12582912.0f;
    int   e = __float_as_int(t) - 0x4B400000;
    float f = y - (t - 12582912.0f);
    float p = 0.00961804886f;
    p = p*f + 0.05550410866f;
    p = p*f + 0.24022650696f;
    p = p*f + 0.69314718056f;
    p = p*f + 1.0f;
    return __int_as_float(__float_as_int(p) + (e << 23));
}

__device__ __forceinline__ void mma16816(float c[4], const uint32_t a[4],
                                         uint32_t b0, uint32_t b1){
    asm volatile(
        "mma.sync.aligned.m16n8k16.row.col.f32.bf16.bf16.f32 "
        "{%0,%1,%2,%3}, {%4,%5,%6,%7}, {%8,%9}, {%0,%1,%2,%3};"
        : "+f"(c[0]), "+f"(c[1]), "+f"(c[2]), "+f"(c[3])
        : "r"(a[0]), "r"(a[1]), "r"(a[2]), "r"(a[3]), "r"(b0), "r"(b1));
}
__device__ __forceinline__ void mma16816h(float c[4], const uint32_t a[4],
                                          uint32_t b0, uint32_t b1){
    asm volatile(
        "mma.sync.aligned.m16n8k16.row.col.f32.f16.f16.f32 "
        "{%0,%1,%2,%3}, {%4,%5,%6,%7}, {%8,%9}, {%0,%1,%2,%3};"
        : "+f"(c[0]), "+f"(c[1]), "+f"(c[2]), "+f"(c[3])
        : "r"(a[0]), "r"(a[1]), "r"(a[2]), "r"(a[3]), "r"(b0), "r"(b1));
}

__device__ __forceinline__ void ldsm_x4(uint32_t r[4], uint32_t addr){
    asm volatile("ldmatrix.sync.aligned.m8n8.x4.shared.b16 {%0,%1,%2,%3}, [%4];"
        : "=r"(r[0]), "=r"(r[1]), "=r"(r[2]), "=r"(r[3]) : "r"(addr));
}

#define CPA16(d, s) asm volatile("cp.async.cg.shared.global [%0], [%1], 16;" \
        :: "r"((uint32_t)(d)), "l"(s) : "memory")
#define CPCOMMIT()  asm volatile("cp.async.commit_group;" ::: "memory")
#define CPWAIT0()   asm volatile("cp.async.wait_group 0;" ::: "memory")

// ---------------- K0: zero accumulators ----------------
__global__ void DNL_k0_zero(){
    int i = blockIdx.x*blockDim.x + threadIdx.x;
    if (i < BB*NNq) g_rowsum[i] = 0.0f;
    if (i < BB*64){ g_qsum[i] = 0.0f; g_ksum[i] = 0.0f; }
}

// ---------------- K1: output-split conv kernel ----------------------------------
// grid (32 n-tiles, 4 b, 2 halves), 256 threads, dyn smem 66560 B
// half 0: q (+qsum), k (+ksum).  half 1: m, v->fp16, BN(wx)->out.
__device__ __forceinline__ void conv_acc(const float* __restrict__ wsm,
                                         const float* __restrict__ xs,
                                         const float* __restrict__ bias,
                                         int o0, int n0, float acc[4][8]){
    #pragma unroll
    for (int i=0;i<4;i++){
        float bv = bias[o0+i];
        #pragma unroll
        for (int j=0;j<8;j++) acc[i][j] = bv;
    }
    #pragma unroll 8
    for (int c=0;c<64;c++){
        float4 x0 = *(const float4*)(xs + (c<<7) + n0);
        float4 x1 = *(const float4*)(xs + (c<<7) + n0 + 4);
        #pragma unroll
        for (int i=0;i<4;i++){
            float w = wsm[(o0+i)*65 + c];
            acc[i][0] += w*x0.x; acc[i][1] += w*x0.y;
            acc[i][2] += w*x0.z; acc[i][3] += w*x0.w;
            acc[i][4] += w*x1.x; acc[i][5] += w*x1.y;
            acc[i][6] += w*x1.z; acc[i][7] += w*x1.w;
        }
    }
}

__global__ __launch_bounds__(256) void DNL_k1(
    const float* __restrict__ x,
    const float* __restrict__ qw, const float* __restrict__ qb,
    const float* __restrict__ kw, const float* __restrict__ kb,
    const float* __restrict__ mw, const float* __restrict__ mb,
    const float* __restrict__ vw, const float* __restrict__ vb,
    const float* __restrict__ ww, const float* __restrict__ wb,
    const float* __restrict__ bng, const float* __restrict__ bnb,
    const float* __restrict__ bnrm, const float* __restrict__ bnrv,
    float* __restrict__ out)
{
    extern __shared__ float sm[];
    float* xs = sm;               // 64*128 = 8192
    float* w0 = xs + 8192;        // 64*65
    float* w1 = w0 + 4160;        // 64*65
    float* qs = w1 + 4160;        // 64
    float* ks = qs + 64;          // 64

    int b = blockIdx.y, nt = blockIdx.x, half = blockIdx.z;
    int nb = nt << 7;
    int tid = threadIdx.x;

    const float* wA = half ? vw : qw;
    const float* wB = half ? ww : kw;

    if (!half && tid < 64){ qs[tid] = 0.0f; ks[tid] = 0.0f; }
    for (int idx = tid; idx < 64*128; idx += 256){
        int c = idx >> 7, pos = idx & 127;
        xs[idx] = x[(((b<<6)+c)<<12) + nb + pos];
    }
    for (int idx = tid; idx < 64*64; idx += 256){
        int o = idx >> 6, c = idx & 63;
        int so = o*65 + c;
        w0[so] = wA[idx]; w1[so] = wB[idx];
    }
    __syncthreads();

    if (half && tid < 128){
        float a = mb[0];
        #pragma unroll 8
        for (int c=0;c<64;c++) a += mw[c]*xs[(c<<7) + tid];
        g_m[(b<<12) + nb + tid] = a;
    }

    int tx = tid & 15, ty = tid >> 4;
    int n0 = tx << 3, o0 = ty << 2;
    float acc[4][8];

    if (!half){
        // Q
        conv_acc(w0, xs, qb, o0, n0, acc);
        #pragma unroll
        for (int i=0;i<4;i++){
            float* dst = g_q + ((((size_t)(b<<6)+o0+i)<<12) + nb + n0);
            *(float4*)dst     = make_float4(acc[i][0],acc[i][1],acc[i][2],acc[i][3]);
            *(float4*)(dst+4) = make_float4(acc[i][4],acc[i][5],acc[i][6],acc[i][7]);
            float s = acc[i][0]+acc[i][1]+acc[i][2]+acc[i][3]
                     +acc[i][4]+acc[i][5]+acc[i][6]+acc[i][7];
            atomicAdd(&qs[o0+i], s);
        }
        // K
        conv_acc(w1, xs, kb, o0, n0, acc);
        #pragma unroll
        for (int i=0;i<4;i++){
            float* dst = g_k + ((((size_t)(b<<6)+o0+i)<<12) + nb + n0);
            *(float4*)dst     = make_float4(acc[i][0],acc[i][1],acc[i][2],acc[i][3]);
            *(float4*)(dst+4) = make_float4(acc[i][4],acc[i][5],acc[i][6],acc[i][7]);
            float s = acc[i][0]+acc[i][1]+acc[i][2]+acc[i][3]
                     +acc[i][4]+acc[i][5]+acc[i][6]+acc[i][7];
            atomicAdd(&ks[o0+i], s);
        }
        __syncthreads();
        if (tid < 64){
            atomicAdd(&g_qsum[(b<<6)+tid], qs[tid]);
            atomicAdd(&g_ksum[(b<<6)+tid], ks[tid]);
        }
    } else {
        // V -> fp16
        conv_acc(w0, xs, vb, o0, n0, acc);
        #pragma unroll
        for (int i=0;i<4;i++){
            __half* dst = g_vF16 + ((((size_t)(b<<6)+o0+i)<<12) + nb + n0);
            __half2 h0 = __floats2half2_rn(acc[i][0], acc[i][1]);
            __half2 h1 = __floats2half2_rn(acc[i][2], acc[i][3]);
            __half2 h2 = __floats2half2_rn(acc[i][4], acc[i][5]);
            __half2 h3 = __floats2half2_rn(acc[i][6], acc[i][7]);
            uint4 pk;
            pk.x = *(uint32_t*)&h0; pk.y = *(uint32_t*)&h1;
            pk.z = *(uint32_t*)&h2; pk.w = *(uint32_t*)&h3;
            *(uint4*)dst = pk;
        }
        // W + BatchNorm -> out
        conv_acc(w1, xs, wb, o0, n0, acc);
        #pragma unroll
        for (int i=0;i<4;i++){
            int o = o0 + i;
            float sc = bng[o] * rsqrtf(bnrv[o] + 1e-5f);
            float sh = bnb[o] - bnrm[o]*sc;
            float* dst = out + (((size_t)(b<<6)+o)<<12) + nb + n0;
            *(float4*)dst     = make_float4(acc[i][0]*sc+sh, acc[i][1]*sc+sh,
                                            acc[i][2]*sc+sh, acc[i][3]*sc+sh);
            *(float4*)(dst+4) = make_float4(acc[i][4]*sc+sh, acc[i][5]*sc+sh,
                                            acc[i][6]*sc+sh, acc[i][7]*sc+sh);
        }
    }
}

// ---------------- K2b: whiten + transpose + bf16 -------------------------------
__global__ __launch_bounds__(256) void DNL_k2b(){
    __shared__ float sq[64*65], sk[64*65], mq[64], mk[64];
    int b = blockIdx.y, nt = blockIdx.x, tid = threadIdx.x;
    if (tid<64){ mq[tid]=g_qsum[(b<<6)+tid]*(1.f/NNq); mk[tid]=g_ksum[(b<<6)+tid]*(1.f/NNq); }
    for (int i=tid;i<4096;i+=256){
        int c=i>>6, n=i&63;
        sq[c*65+n]=g_q[(((size_t)(b<<6)+c)<<12)+(nt<<6)+n];
        sk[c*65+n]=g_k[(((size_t)(b<<6)+c)<<12)+(nt<<6)+n];
    }
    __syncthreads();
    for (int i=tid;i<2048;i+=256){
        int n=i>>5, c=(i&31)<<1;
        size_t row = (size_t)(b<<12)+(nt<<6)+n;
        __nv_bfloat162 hq = __floats2bfloat162_rn(sq[c*65+n]-mq[c], sq[(c+1)*65+n]-mq[c+1]);
        __nv_bfloat162 hk = __floats2bfloat162_rn(sk[c*65+n]-mk[c], sk[(c+1)*65+n]-mk[c+1]);
        *(__nv_bfloat162*)(g_qTb + row*64 + c) = hq;
        *(__nv_bfloat162*)(g_kTb + row*64 + c) = hk;
    }
}

// ---------------- K3r: rowsums only, cp.async double-buffered Q -----------------
// grid (jh=4, it=32, b=4) = 512 blocks, 256 threads, dyn smem 55296 B
__global__ __launch_bounds__(256) void DNL_k3r(){
    extern __shared__ char s3[];
    uint32_t sA = (uint32_t)__cvta_generic_to_shared(s3);
    int jh=blockIdx.x, it=blockIdx.y, b=blockIdx.z;
    int tid=threadIdx.x;
    int w = tid>>5, lane = tid&31, g = lane>>2, t = lane&3;
    int wn = w<<4;

    uint32_t aAddr = sA + (uint32_t)((wn + (lane&7) + ((lane>>3)&1)*8)*144
                                     + ((lane>>4)&1)*16);
    uint32_t bRel  = (uint32_t)(((lane&7) + (lane>>4)*8)*144 + ((lane>>3)&1)*16);

    for (int i=tid;i<1024;i+=256){
        int r=i>>3, u=i&7;
        CPA16(sA + r*144 + u*16,
              g_kTb + ((size_t)(b<<12)+(it<<7)+r)*64 + u*8);
    }
    for (int i=tid;i<1024;i+=256){
        int r=i>>3, u=i&7;
        CPA16(sA + 18432 + r*144 + u*16,
              g_qTb + ((size_t)(b<<12)+(jh<<10)+r)*64 + u*8);
    }
    CPCOMMIT();

    float rs0=0.f, rs1=0.f;
    for (int mc2=0; mc2<8; mc2++){
        CPWAIT0();
        __syncthreads();
        if (mc2 < 7){
            uint32_t dst = sA + 18432 + (((mc2+1)&1) ? 18432u : 0u);
            for (int i=tid;i<1024;i+=256){
                int r=i>>3, u=i&7;
                CPA16(dst + r*144 + u*16,
                      g_qTb + ((size_t)(b<<12)+(jh<<10)+((mc2+1)<<7)+r)*64 + u*8);
            }
            CPCOMMIT();
        }
        uint32_t bAddr = sA + 18432 + ((mc2&1) ? 18432u : 0u) + bRel;

        float a[16][4];
        #pragma unroll
        for (int cs=0;cs<16;cs++){ a[cs][0]=0.f; a[cs][1]=0.f; a[cs][2]=0.f; a[cs][3]=0.f; }
        #pragma unroll
        for (int k=0;k<4;k++){
            uint32_t af[4];
            ldsm_x4(af, aAddr + k*32);
            #pragma unroll
            for (int u=0;u<8;u++){
                uint32_t bf[4];
                ldsm_x4(bf, bAddr + u*(16*144) + k*32);
                mma16816(a[2*u],   af, bf[0], bf[1]);
                mma16816(a[2*u+1], af, bf[2], bf[3]);
            }
        }
        #pragma unroll
        for (int cs=0;cs<16;cs++){
            rs0 += fexp(a[cs][0]) + fexp(a[cs][1]);
            rs1 += fexp(a[cs][2]) + fexp(a[cs][3]);
        }
    }
    rs0 += __shfl_xor_sync(0xffffffffu, rs0, 1);
    rs0 += __shfl_xor_sync(0xffffffffu, rs0, 2);
    rs1 += __shfl_xor_sync(0xffffffffu, rs1, 1);
    rs1 += __shfl_xor_sync(0xffffffffu, rs1, 2);
    if (t == 0){
        atomicAdd(&g_rowsum[(b<<12)+(it<<7)+wn+g],   rs0);
        atomicAdd(&g_rowsum[(b<<12)+(it<<7)+wn+g+8], rs1);
    }
}

// ---------------- K3b: reciprocal row sums --------------------------------------
__global__ void DNL_k3b(){
    int i = blockIdx.x*blockDim.x + threadIdx.x;
    if (i < BB*NNq) g_invrs[i] = 1.0f / g_rowsum[i];
}

// ---------------- K3c: P16[b][n][m] = exp(m_b[n]m_b[m]) / sum_b' ----------------
__global__ __launch_bounds__(256) void DNL_k3c(){
    size_t tt = ((size_t)blockIdx.x << 8) + threadIdx.x;   // 8.4M
    int n  = (int)(tt >> 11);
    int m0 = (int)((tt & 2047) << 1);
    float a0=g_m[n], a1=g_m[4096+n], a2=g_m[8192+n], a3=g_m[12288+n];
    float p0=g_m[m0],       q0=g_m[m0+1];
    float p1=g_m[4096+m0],  q1=g_m[4097+m0];
    float p2=g_m[8192+m0],  q2=g_m[8193+m0];
    float p3=g_m[12288+m0], q3=g_m[12289+m0];
    float e00=fexp(a0*p0), e01=fexp(a0*q0);
    float e10=fexp(a1*p1), e11=fexp(a1*q1);
    float e20=fexp(a2*p2), e21=fexp(a2*q2);
    float e30=fexp(a3*p3), e31=fexp(a3*q3);
    float s0=e00+e10+e20+e30, s1=e01+e11+e21+e31;
    float r0 = __int_as_float(0x7EF311C3 - __float_as_int(s0));
    r0 = r0*(2.0f-s0*r0); r0 = r0*(2.0f-s0*r0);
    float r1 = __int_as_float(0x7EF311C3 - __float_as_int(s1));
    r1 = r1*(2.0f-s1*r1); r1 = r1*(2.0f-s1*r1);
    size_t base = ((size_t)n<<12) + m0;
    *(__half2*)(g_P16 + base)               = __floats2half2_rn(e00*r0, e01*r1);
    *(__half2*)(g_P16 + (1ULL<<24) + base)  = __floats2half2_rn(e10*r0, e11*r1);
    *(__half2*)(g_P16 + (2ULL<<24) + base)  = __floats2half2_rn(e20*r0, e21*r1);
    *(__half2*)(g_P16 + (3ULL<<24) + base)  = __floats2half2_rn(e30*r0, e31*r1);
}

// ---------------- K4r: pipelined fused S -> F(+P16) -> out += V*F ---------------
// grid (b=4 fastest, mt=64), 256 threads, dyn smem 74240 B
#define K4_SQ    0
#define K4_SFH   9216
#define K4_ST0   18432
#define K4_ST1   46336
#define K4_STK   0
#define K4_STV   9216
#define K4_STP   18432
#define K4_SIR   27648
// stage size = 27904

__device__ __forceinline__ void k4_issue_stage(uint32_t dstBase, int b, int nbase,
                                               int mbase, int tid){
    for (int i=tid;i<512;i+=256){
        int r=i>>3, u=i&7;
        CPA16(dstBase + K4_STK + r*144 + u*16,
              g_kTb + ((size_t)(b<<12)+nbase+r)*64 + u*8);
    }
    for (int i=tid;i<512;i+=256){
        int c=i>>3, u=i&7;
        CPA16(dstBase + K4_STV + c*144 + u*16,
              g_vF16 + (((size_t)(b<<6)+c)<<12) + nbase + u*8);
    }
    for (int i=tid;i<512;i+=256){
        int r=i>>3, u=i&7;     // row r = local m; symmetric P -> n contiguous
        CPA16(dstBase + K4_STP + r*144 + u*16,
              g_P16 + ((size_t)b<<24) + ((size_t)(mbase+r)<<12) + nbase + u*8);
    }
    if (tid < 16)
        CPA16(dstBase + K4_SIR + tid*16, g_invrs + (b<<12) + nbase + tid*4);
}

__global__ __launch_bounds__(256,2) void DNL_k4r(float* __restrict__ out){
    extern __shared__ char s4[];
    uint32_t sA = (uint32_t)__cvta_generic_to_shared(s4);
    int b = blockIdx.x, mt = blockIdx.y;
    int mbase = mt<<6;
    int tid = threadIdx.x;
    int w = tid>>5, lane = tid&31, g = lane>>2, t = lane&3;
    int wn = (w&3)<<4;
    int wm = (w>>2)<<5;

    uint32_t aRow = (uint32_t)((wn + (lane&7) + ((lane>>3)&1)*8)*144
                               + ((lane>>4)&1)*16);
    uint32_t bRow = (uint32_t)((wm + (lane&7) + (lane>>4)*8)*144
                               + ((lane>>3)&1)*16);
    uint32_t bQ  = sA + K4_SQ  + bRow;
    uint32_t bFH = sA + K4_SFH + bRow;

    // prologue
    for (int i=tid;i<512;i+=256){
        int r=i>>3, u=i&7;
        CPA16(sA + K4_SQ + r*144 + u*16,
              g_qTb + ((size_t)(b<<12)+mbase+r)*64 + u*8);
    }
    k4_issue_stage(sA + K4_ST0, b, 0, mbase, tid);
    CPCOMMIT();

    float acc2[4][4];
    #pragma unroll
    for (int mc=0;mc<4;mc++){ acc2[mc][0]=0.f; acc2[mc][1]=0.f; acc2[mc][2]=0.f; acc2[mc][3]=0.f; }

    for (int ch=0; ch<64; ch++){
        CPWAIT0();
        __syncthreads();   // data landed; all warps past mma2(ch-1)

        int stgOff = (ch&1) ? K4_ST1 : K4_ST0;
        uint32_t stgA = sA + stgOff;
        if (ch < 63){
            k4_issue_stage(sA + (((ch+1)&1) ? K4_ST1 : K4_ST0), b, (ch+1)<<6, mbase, tid);
            CPCOMMIT();
        }

        // ---- mma1: S = K x Q^T (bf16) ----
        float a1[4][4];
        #pragma unroll
        for (int mc=0;mc<4;mc++){ a1[mc][0]=0.f; a1[mc][1]=0.f; a1[mc][2]=0.f; a1[mc][3]=0.f; }
        uint32_t aK = stgA + K4_STK + aRow;
        #pragma unroll
        for (int k=0;k<4;k++){
            uint32_t af[4], bf0[4], bf1[4];
            ldsm_x4(af,  aK + k*32);
            ldsm_x4(bf0, bQ + k*32);
            ldsm_x4(bf1, bQ + 16*144 + k*32);
            mma16816(a1[0], af, bf0[0], bf0[1]);
            mma16816(a1[1], af, bf0[2], bf0[3]);
            mma16816(a1[2], af, bf1[0], bf1[1]);
            mma16816(a1[3], af, bf1[2], bf1[3]);
        }
        // ---- construct F = fexp(S)*irs + P16 -> FH fp16 [m][n] ----
        const __half* Ps   = (const __half*)(s4 + stgOff + K4_STP);
        const float*  irsS = (const float*)(s4 + stgOff + K4_SIR);
        int nl0 = wn+g, nl1 = nl0+8;
        float ir0 = irsS[nl0], ir1 = irsS[nl1];
        __half* FH = (__half*)(s4+K4_SFH);
        #pragma unroll
        for (int mc=0;mc<4;mc++){
            int ml = wm + mc*8 + 2*t;
            float f0 = fexp(a1[mc][0])*ir0 + __half2float(Ps[ml*72     + nl0]);
            float f1 = fexp(a1[mc][1])*ir0 + __half2float(Ps[(ml+1)*72 + nl0]);
            float f2 = fexp(a1[mc][2])*ir1 + __half2float(Ps[ml*72     + nl1]);
            float f3 = fexp(a1[mc][3])*ir1 + __half2float(Ps[(ml+1)*72 + nl1]);
            FH[ml*72     + nl0] = __float2half_rn(f0);
            FH[(ml+1)*72 + nl0] = __float2half_rn(f1);
            FH[ml*72     + nl1] = __float2half_rn(f2);
            FH[(ml+1)*72 + nl1] = __float2half_rn(f3);
        }
        __syncthreads();   // F visible

        // ---- mma2: acc2 += V16 * FH  (fp16, single pass) ----
        uint32_t aV = stgA + K4_STV + aRow;
        #pragma unroll
        for (int k=0;k<4;k++){
            uint32_t ah[4], bh0[4], bh1[4];
            ldsm_x4(ah,  aV + k*32);
            ldsm_x4(bh0, bFH + k*32);
            ldsm_x4(bh1, bFH + 16*144 + k*32);
            mma16816h(acc2[0], ah, bh0[0], bh0[1]);
            mma16816h(acc2[1], ah, bh0[2], bh0[3]);
            mma16816h(acc2[2], ah, bh1[0], bh1[1]);
            mma16816h(acc2[3], ah, bh1[2], bh1[3]);
        }
    }

    // epilogue: RMW onto BN residual
    #pragma unroll
    for (int mc=0;mc<4;mc++){
        int cg = wn + g;
        int mg = mbase + wm + mc*8 + 2*t;
        float* d0 = out + (((size_t)(b<<6)+cg)<<12) + mg;
        float2 o0 = *(const float2*)d0;
        o0.x += acc2[mc][0]; o0.y += acc2[mc][1];
        *(float2*)d0 = o0;
        float* d1 = out + (((size_t)(b<<6)+cg+8)<<12) + mg;
        float2 o1 = *(const float2*)d1;
        o1.x += acc2[mc][2]; o1.y += acc2[mc][3];
        *(float2*)d1 = o1;
    }
}

// ---------------- host launcher -------------------------------------------------
extern "C" void kernel_launch(void* const* d_in, const int* in_sizes, int n_in,
                              void* d_out, int out_size)
{
    const float* x    = (const float*)d_in[0];
    const float* qw   = (const float*)d_in[1];
    const float* qb   = (const float*)d_in[2];
    const float* kw   = (const float*)d_in[3];
    const float* kb   = (const float*)d_in[4];
    const float* mw   = (const float*)d_in[5];
    const float* mb   = (const float*)d_in[6];
    const float* vw   = (const float*)d_in[7];
    const float* vb   = (const float*)d_in[8];
    const float* ww   = (const float*)d_in[9];
    const float* wb   = (const float*)d_in[10];
    const float* bng  = (const float*)d_in[11];
    const float* bnb  = (const float*)d_in[12];
    const float* bnrm = (const float*)d_in[13];
    const float* bnrv = (const float*)d_in[14];
    float* out = (float*)d_out;

    const int SM1 = 66560;
    const int SM3 = 55296;
    const int SM4 = 74240;
    cudaFuncSetAttribute(DNL_k1,  cudaFuncAttributeMaxDynamicSharedMemorySize, SM1);
    cudaFuncSetAttribute(DNL_k3r, cudaFuncAttributeMaxDynamicSharedMemorySize, SM3);
    cudaFuncSetAttribute(DNL_k4r, cudaFuncAttributeMaxDynamicSharedMemorySize, SM4);

    DNL_k0_zero<<<64, 256>>>();
    DNL_k1<<<dim3(32,4,2), 256, SM1>>>(x, qw,qb, kw,kb, mw,mb, vw,vb, ww,wb,
                                       bng,bnb,bnrm,bnrv, out);
    DNL_k2b<<<dim3(64,4), 256>>>();
    DNL_k3r<<<dim3(4,32,4), 256, SM3>>>();
    DNL_k3b<<<64, 256>>>();
    DNL_k3c<<<32768, 256>>>();
    DNL_k4r<<<dim3(4,64), 256, SM4>>>(out);
}